// round 9
// baseline (speedup 1.0000x reference)
#include <cuda_runtime.h>

#define N_TOT   16384      // B*H*W
#define C_DIM   256
#define K_CODES 8192
#define HW      1024
#define B_DIM   16

#define BM 128
#define BN 256
#define BK 8
#define TM 4
#define TN 16

// Device scratch (no allocations allowed in kernel_launch)
__device__ float g_ztT [C_DIM * N_TOT];    // [C][N]  z transposed: 16 MB
__device__ float g_embT[C_DIM * K_CODES];  // [C][K]  emb transposed: 8 MB
__device__ float g_ehalf[K_CODES];         // 0.5*||e_k||^2
__device__ int   g_idx  [N_TOT];           // argmin indices

// ---------------------------------------------------------------------------
// Pass 1: z [B][C][HW] -> ztT [C][B*HW].
// ---------------------------------------------------------------------------
__global__ void k_zt(const float* __restrict__ z) {
    int idx = blockIdx.x * blockDim.x + threadIdx.x;   // (b,c,hw)
    int hw = idx & (HW - 1);
    int c  = (idx >> 10) & (C_DIM - 1);
    int b  = idx >> 18;
    g_ztT[c * N_TOT + b * HW + hw] = z[idx];
}

// ---------------------------------------------------------------------------
// Pass 2: embT[c][k] = emb[k][c].  Tiled 32x32 transpose.
// ---------------------------------------------------------------------------
__global__ void k_embT(const float* __restrict__ emb) {
    __shared__ float tile[32][33];
    int c0 = blockIdx.x * 32;
    int k0 = blockIdx.y * 32;
    int tx = threadIdx.x, ty = threadIdx.y;
    #pragma unroll
    for (int i = 0; i < 32; i += 8)
        tile[ty + i][tx] = emb[(k0 + ty + i) * C_DIM + c0 + tx];
    __syncthreads();
    #pragma unroll
    for (int i = 0; i < 32; i += 8)
        g_embT[(c0 + ty + i) * K_CODES + k0 + tx] = tile[tx][ty + i];
}

// ---------------------------------------------------------------------------
// Pass 3: g_ehalf[k] = 0.5 * ||e_k||^2.  One warp per code.
// ---------------------------------------------------------------------------
__global__ void k_ehalf(const float* __restrict__ emb) {
    int k    = blockIdx.x * (blockDim.x >> 5) + (threadIdx.x >> 5);
    int lane = threadIdx.x & 31;
    const float* row = emb + k * C_DIM;
    float s = 0.0f;
    #pragma unroll
    for (int c = lane; c < C_DIM; c += 32) { float v = row[c]; s = fmaf(v, v, s); }
    #pragma unroll
    for (int off = 16; off; off >>= 1) s += __shfl_xor_sync(0xffffffffu, s, off);
    if (lane == 0) g_ehalf[k] = 0.5f * s;
}

// ---------------------------------------------------------------------------
// Main: fused fp32 GEMM + running argmax.
//   score[m][k] = z_m . e_k - 0.5*||e_k||^2 ; idx[m] = argmax_k score
// CTA: 128 rows x (32 tiles of 256 codes), 512 threads, 4x16 micro-tile.
// Double-buffered smem (8 C-rows/chunk), register-staged global prefetch.
// Accumulation order over C identical to R3 kernel -> bit-identical scores.
// ---------------------------------------------------------------------------
__global__ __launch_bounds__(512, 1) void k_main() {
    __shared__ float As[2][BK][BM];   // 8 KB
    __shared__ float Bs[2][BK][BN];   // 16 KB

    const int tid  = threadIdx.x;
    const int m0   = blockIdx.x * BM;
    const int tx   = tid & 15;        // code-group thread (16)
    const int ty   = tid >> 4;        // row-group thread (32)
    const int row0 = ty * TM;         // 4 rows per thread
    const int cb   = tx * 4;          // float4 base within each 64-code block

    // smem-fill assignments (all coalesced LDG.128 / dense STS.128)
    const int  b_r  = tid >> 6;              // 0..7
    const int  b_c  = (tid & 63) << 2;       // 0..252
    const int  a_r  = (tid & 255) >> 5;      // 0..7
    const int  a_c  = (tid & 31) << 2;       // 0..124
    const bool do_a = tid < 256;

    float best[TM];
    int   bidx[TM];
    #pragma unroll
    for (int i = 0; i < TM; i++) { best[i] = -1e30f; bidx[i] = 0; }

    // prefetch step u=0 (t=0, q=0)
    if (do_a)
        *(float4*)&As[0][a_r][a_c] = *(const float4*)&g_ztT [a_r * N_TOT   + m0 + a_c];
    *(float4*)&Bs[0][b_r][b_c]     = *(const float4*)&g_embT[b_r * K_CODES +      b_c];
    __syncthreads();

    int buf = 0;
    for (int t = 0; t < 32; ++t) {
        const int k0 = t * BN;

        // fold -0.5||e||^2 into accumulator init
        float acc[TM][TN];
        #pragma unroll
        for (int j4 = 0; j4 < 4; ++j4) {
            float4 e = *(const float4*)&g_ehalf[k0 + j4 * 64 + cb];
            #pragma unroll
            for (int i = 0; i < TM; i++) {
                acc[i][j4 * 4 + 0] = -e.x;
                acc[i][j4 * 4 + 1] = -e.y;
                acc[i][j4 * 4 + 2] = -e.z;
                acc[i][j4 * 4 + 3] = -e.w;
            }
        }

        for (int q = 0; q < 32; ++q) {
            const bool has_next = (t * 32 + q != 1023);
            float4 na, nb;
            if (has_next) {
                int qn = (q == 31) ? 0 : q + 1;
                int tn = (q == 31) ? t + 1 : t;
                int cn = qn << 3;
                int kn = tn * BN;
                if (do_a)
                    na = *(const float4*)&g_ztT [(cn + a_r) * N_TOT   + m0 + a_c];
                nb     = *(const float4*)&g_embT[(cn + b_r) * K_CODES + kn + b_c];
            }
            #pragma unroll
            for (int cc = 0; cc < BK; ++cc) {
                float a[TM], b[TN];
                *(float4*)&a[0] = *(const float4*)&As[buf][cc][row0];
                #pragma unroll
                for (int j4 = 0; j4 < 4; ++j4)
                    *(float4*)&b[j4 * 4] = *(const float4*)&Bs[buf][cc][j4 * 64 + cb];
                #pragma unroll
                for (int i = 0; i < TM; i++)
                    #pragma unroll
                    for (int j = 0; j < TN; j++)
                        acc[i][j] = fmaf(a[i], b[j], acc[i][j]);
            }
            if (has_next) {
                if (do_a)
                    *(float4*)&As[buf ^ 1][a_r][a_c] = na;
                *(float4*)&Bs[buf ^ 1][b_r][b_c]     = nb;
            }
            __syncthreads();
            buf ^= 1;
        }

        // per-thread running argmax; codes visited in increasing global order
        // (strict > keeps lowest index on ties, matching jnp.argmin)
        #pragma unroll
        for (int j4 = 0; j4 < 4; ++j4)
            #pragma unroll
            for (int jj = 0; jj < 4; ++jj) {
                const int code = k0 + j4 * 64 + cb + jj;
                #pragma unroll
                for (int i = 0; i < TM; i++) {
                    float v = acc[i][j4 * 4 + jj];
                    if (v > best[i]) { best[i] = v; bidx[i] = code; }
                }
            }
    }

    // reduce across the 16 tx-threads sharing each row (width-16 butterfly)
    #pragma unroll
    for (int i = 0; i < TM; i++) {
        float v  = best[i];
        int   ix = bidx[i];
        #pragma unroll
        for (int off = 8; off; off >>= 1) {
            float v2 = __shfl_xor_sync(0xffffffffu, v,  off, 16);
            int   x2 = __shfl_xor_sync(0xffffffffu, ix, off, 16);
            if (v2 > v || (v2 == v && x2 < ix)) { v = v2; ix = x2; }
        }
        if (tx == 0) g_idx[m0 + row0 + i] = ix;
    }
}

// ---------------------------------------------------------------------------
// Gather: out[b][c][hw] = emb[idx[b*HW+hw]][c].
// ---------------------------------------------------------------------------
__global__ void k_gather(const float* __restrict__ emb, float* __restrict__ out) {
    __shared__ float tile[32 * 257];
    __shared__ int   sidx[32];
    const int nb  = blockIdx.x * 32;
    const int tid = threadIdx.x;
    if (tid < 32) sidx[tid] = g_idx[nb + tid];
    __syncthreads();

    const int w = tid >> 5, lane = tid & 31;
    #pragma unroll
    for (int r = w * 4; r < w * 4 + 4; ++r) {
        const float* src = emb + (size_t)sidx[r] * C_DIM;
        #pragma unroll
        for (int c = lane; c < C_DIM; c += 32)
            tile[r * 257 + c] = src[c];
    }
    __syncthreads();

    const int b   = nb >> 10;
    const int hw0 = nb & (HW - 1);
    const int cg  = tid >> 5;   // 0..7
    #pragma unroll
    for (int c = cg; c < C_DIM; c += 8)
        out[b * (C_DIM * HW) + c * HW + hw0 + lane] = tile[lane * 257 + c];
}

// ---------------------------------------------------------------------------
extern "C" void kernel_launch(void* const* d_in, const int* in_sizes, int n_in,
                              void* d_out, int out_size) {
    const float* z   = (const float*)d_in[0];   // [16,256,32,32] fp32
    const float* emb = (const float*)d_in[1];   // [8192,256] fp32
    float* out = (float*)d_out;                 // [16,256,32,32] fp32

    k_zt    <<<(B_DIM * C_DIM * HW) / 256, 256>>>(z);
    k_embT  <<<dim3(C_DIM / 32, K_CODES / 32), dim3(32, 8)>>>(emb);
    k_ehalf <<<K_CODES / 8, 256>>>(emb);
    k_main  <<<N_TOT / BM, 512>>>();
    k_gather<<<N_TOT / 32, 256>>>(emb, out);
}

// round 11
// speedup vs baseline: 2.0173x; 2.0173x over previous
#include <cuda_runtime.h>
#include <stdint.h>

#define NTOT  16384      // B*H*W query rows
#define CDIM  256
#define KCOD  8192
#define HW    1024
#define BD    16
#define KEFF  768        // 3 tf32 segments x 256
#define NCHUNK 24        // KEFF / 32
#define NTILE  64        // KCOD / 128
#define TOTSTEP (NTILE * NCHUNK)   // 1536

// ---- device scratch ----
__device__ float g_Ap[(size_t)NTOT * KEFF];   // 48MB  [n][768] permuted (zhi|zhi|zlo)
__device__ float g_Bp[(size_t)KCOD * KEFF];   // 24MB  [k][768] permuted (ehi|elo|ehi)
__device__ float g_eh[KCOD];                  // 0.5*||e||^2
__device__ int   g_idx[NTOT];

// ---------------------------------------------------------------------------
__device__ __forceinline__ uint32_t smem_u32(const void* p) {
    uint32_t a;
    asm("{ .reg .u64 t; cvta.to.shared.u64 t, %1; cvt.u32.u64 %0, t; }"
        : "=r"(a) : "l"(p));
    return a;
}
__device__ __forceinline__ float to_tf32(float x) {
    float r;
    asm("cvt.rna.tf32.f32 %0, %1;" : "=f"(r) : "f"(x));
    return r;
}
__device__ __forceinline__ void cpa16(uint32_t s, const void* g) {
    asm volatile("cp.async.cg.shared.global [%0], [%1], 16;"
                 :: "r"(s), "l"(g) : "memory");
}
// fragment slot permutation within each k8 group: slot = 2*(k&3) + (k>>2)
__device__ __forceinline__ int slot_of(int u) {
    return (u & ~7) | (((u & 3) << 1) | ((u >> 2) & 1));
}
__device__ __forceinline__ void mma8(float* d, float a0, float a1, float a2,
                                     float a3, float b0, float b1) {
    asm volatile(
        "mma.sync.aligned.m16n8k8.row.col.f32.tf32.tf32.f32 "
        "{%0,%1,%2,%3},{%4,%5,%6,%7},{%8,%9},{%0,%1,%2,%3};"
        : "+f"(d[0]), "+f"(d[1]), "+f"(d[2]), "+f"(d[3])
        : "r"(__float_as_uint(a0)), "r"(__float_as_uint(a1)),
          "r"(__float_as_uint(a2)), "r"(__float_as_uint(a3)),
          "r"(__float_as_uint(b0)), "r"(__float_as_uint(b1)));
}

// ---------------------------------------------------------------------------
// Prep: z [B,C,HW] -> g_Ap rows (tf32 hi,hi,lo), fragment-permuted
// ---------------------------------------------------------------------------
__global__ void k_prep_z(const float* __restrict__ z) {
    __shared__ float t[32][33];
    const int c0 = blockIdx.x * 32, hw0 = blockIdx.y * 32, b = blockIdx.z;
    const int tx = threadIdx.x, ty = threadIdx.y;
    #pragma unroll
    for (int i = 0; i < 32; i += 8)
        t[ty + i][tx] = z[((size_t)b * CDIM + c0 + ty + i) * HW + hw0 + tx];
    __syncthreads();
    #pragma unroll
    for (int i = 0; i < 32; i += 8) {
        float v  = t[tx][ty + i];             // z[c0+tx][hw0+ty+i]
        float hi = to_tf32(v);
        float lo = to_tf32(v - hi);
        int   c  = c0 + tx;
        size_t n = (size_t)b * HW + hw0 + ty + i;
        float* r = g_Ap + n * KEFF;
        r[slot_of(c)]       = hi;
        r[slot_of(256 + c)] = hi;
        r[slot_of(512 + c)] = lo;
    }
}

// emb [K,C] -> g_Bp rows (ehi, elo, ehi), fragment-permuted
__global__ void k_prep_e(const float* __restrict__ emb) {
    int i = blockIdx.x * 256 + threadIdx.x;
    int k = i >> 8, c = i & 255;
    float v  = emb[i];
    float hi = to_tf32(v);
    float lo = to_tf32(v - hi);
    float* r = g_Bp + (size_t)k * KEFF;
    r[slot_of(c)]       = hi;
    r[slot_of(256 + c)] = lo;
    r[slot_of(512 + c)] = hi;
}

// g_eh[k] = 0.5*||e_k||^2 (fp32)
__global__ void k_ehalf(const float* __restrict__ emb) {
    int k    = blockIdx.x * (blockDim.x >> 5) + (threadIdx.x >> 5);
    int lane = threadIdx.x & 31;
    const float* row = emb + (size_t)k * CDIM;
    float s = 0.0f;
    #pragma unroll
    for (int c = lane; c < CDIM; c += 32) { float v = row[c]; s = fmaf(v, v, s); }
    #pragma unroll
    for (int off = 16; off; off >>= 1) s += __shfl_xor_sync(0xffffffffu, s, off);
    if (lane == 0) g_eh[k] = 0.5f * s;
}

// ---------------------------------------------------------------------------
// Main: mma.sync tf32 3-product GEMM + fused running argmax.
// CTA: 128 queries x 64 tiles of 128 codes, K=768, 8 warps (warp tile 32x64).
// 4-stage cp.async ring (4 x 32KB), XOR-swizzled for conflict-free LDS.64.
// ---------------------------------------------------------------------------
__global__ __launch_bounds__(256, 1) void k_main() {
    extern __shared__ float sm[];   // 4 stages * 8192 floats (A 4096 | B 4096)
    const int tid  = threadIdx.x;
    const int lane = tid & 31, wid = tid >> 5;
    const int wm = wid & 3, wn = wid >> 2;
    const int g = lane >> 2, tig = lane & 3;
    const int tig2 = tig >> 1, tig1 = tig & 1;
    const int m0 = blockIdx.x * 128;
    const uint32_t smb = smem_u32(sm);

    float acc[2][8][4];
    float bestv[2][2];
    int   besti[2][2];
    #pragma unroll
    for (int a = 0; a < 2; a++)
        #pragma unroll
        for (int h = 0; h < 2; h++) { bestv[a][h] = -1e30f; besti[a][h] = 0; }

    // stage filler: A tile 128 rows x 32 floats, B tile 128 rows x 32 floats
    auto issue = [&](int s) {
        int tile = s / NCHUNK, chunk = s - tile * NCHUNK;
        int u0 = chunk * 32;
        uint32_t stg = smb + (uint32_t)(s & 3) * 32768u;
        const float* Ag = g_Ap + (size_t)m0 * KEFF + u0;
        const float* Bg = g_Bp + (size_t)(tile * 128) * KEFF + u0;
        #pragma unroll
        for (int it = 0; it < 4; ++it) {
            int cidx = it * 256 + tid;
            int row = cidx >> 3, lc = cidx & 7;
            uint32_t d = stg + (uint32_t)row * 128u +
                         (uint32_t)((lc ^ ((row & 3) << 1)) << 4);
            cpa16(d,          Ag + (size_t)row * KEFF + lc * 4);
            cpa16(d + 16384u, Bg + (size_t)row * KEFF + lc * 4);
        }
    };
    // fragment-pair load (LDS.64, conflict-free by construction)
    auto ldp = [&](const float* base, int row, int l) -> float2 {
        int pc = (2 * l + tig2) ^ ((row & 3) << 1);
        return *(const float2*)(base + row * 32 + pc * 4 + tig1 * 2);
    };

    issue(0); asm volatile("cp.async.commit_group;" ::: "memory");
    issue(1); asm volatile("cp.async.commit_group;" ::: "memory");

    for (int s = 0; s < TOTSTEP; ++s) {
        const int tile = s / NCHUNK;
        const int chunk = s - tile * NCHUNK;
        if (chunk == 0) {
            #pragma unroll
            for (int mi = 0; mi < 2; mi++)
                #pragma unroll
                for (int ni = 0; ni < 8; ni++)
                    #pragma unroll
                    for (int r = 0; r < 4; r++) acc[mi][ni][r] = 0.0f;
        }
        if (s + 2 < TOTSTEP) issue(s + 2);
        asm volatile("cp.async.commit_group;" ::: "memory");
        asm volatile("cp.async.wait_group 2;" ::: "memory");
        __syncthreads();

        const float* stA = sm + (s & 3) * 8192;
        const float* stB = stA + 4096;
        #pragma unroll
        for (int l = 0; l < 4; ++l) {
            float2 fa[2][2];
            #pragma unroll
            for (int mi = 0; mi < 2; ++mi) {
                int r0 = wm * 32 + mi * 16 + g;
                fa[mi][0] = ldp(stA, r0, l);       // row g   : (a0, a2)
                fa[mi][1] = ldp(stA, r0 + 8, l);   // row g+8 : (a1, a3)
            }
            float2 fb[8];
            #pragma unroll
            for (int ni = 0; ni < 8; ++ni)
                fb[ni] = ldp(stB, wn * 64 + ni * 8 + g, l);   // (b0, b1)
            #pragma unroll
            for (int mi = 0; mi < 2; ++mi)
                #pragma unroll
                for (int ni = 0; ni < 8; ++ni)
                    mma8(acc[mi][ni], fa[mi][0].x, fa[mi][1].x,
                         fa[mi][0].y, fa[mi][1].y, fb[ni].x, fb[ni].y);
        }

        if (chunk == NCHUNK - 1) {
            // epilogue: subtract 0.5||e||^2, update running argmax
            const int k0 = tile * 128;
            #pragma unroll
            for (int ni = 0; ni < 8; ++ni) {
                int colg = k0 + wn * 64 + ni * 8 + 2 * tig;
                float e0 = __ldg(&g_eh[colg]);
                float e1 = __ldg(&g_eh[colg + 1]);
                #pragma unroll
                for (int mi = 0; mi < 2; ++mi) {
                    float v;
                    v = acc[mi][ni][0] - e0;
                    if (v > bestv[mi][0]) { bestv[mi][0] = v; besti[mi][0] = colg; }
                    v = acc[mi][ni][1] - e1;
                    if (v > bestv[mi][0]) { bestv[mi][0] = v; besti[mi][0] = colg + 1; }
                    v = acc[mi][ni][2] - e0;
                    if (v > bestv[mi][1]) { bestv[mi][1] = v; besti[mi][1] = colg; }
                    v = acc[mi][ni][3] - e1;
                    if (v > bestv[mi][1]) { bestv[mi][1] = v; besti[mi][1] = colg + 1; }
                }
            }
        }
    }

    // ---- final argmax merge ----
    __syncthreads();
    float* sval = sm;                 // [wn][128]
    int*   sidx = (int*)(sm + 256);   // [wn][128]
    #pragma unroll
    for (int mi = 0; mi < 2; ++mi)
        #pragma unroll
        for (int h = 0; h < 2; ++h) {
            float v  = bestv[mi][h];
            int   ix = besti[mi][h];
            #pragma unroll
            for (int off = 1; off <= 2; off <<= 1) {
                float v2 = __shfl_xor_sync(0xffffffffu, v,  off);
                int   i2 = __shfl_xor_sync(0xffffffffu, ix, off);
                if (v2 > v || (v2 == v && i2 < ix)) { v = v2; ix = i2; }
            }
            if (tig == 0) {
                int r = wm * 32 + mi * 16 + g + 8 * h;
                sval[wn * 128 + r] = v;
                sidx[wn * 128 + r] = ix;
            }
        }
    __syncthreads();
    if (tid < 128) {
        float a = sval[tid], b2 = sval[128 + tid];
        int  ia = sidx[tid], ib = sidx[128 + tid];
        g_idx[m0 + tid] = (b2 > a || (b2 == a && ib < ia)) ? ib : ia;
    }
}

// ---------------------------------------------------------------------------
// Gather: out[b][c][hw] = emb[idx[b*HW+hw]][c].
// ---------------------------------------------------------------------------
__global__ void k_gather(const float* __restrict__ emb, float* __restrict__ out) {
    __shared__ float tile[32 * 257];
    __shared__ int   sidx[32];
    const int nb  = blockIdx.x * 32;
    const int tid = threadIdx.x;
    if (tid < 32) sidx[tid] = g_idx[nb + tid];
    __syncthreads();

    const int w = tid >> 5, lane = tid & 31;
    #pragma unroll
    for (int r = w * 4; r < w * 4 + 4; ++r) {
        const float* src = emb + (size_t)sidx[r] * CDIM;
        #pragma unroll
        for (int c = lane; c < CDIM; c += 32)
            tile[r * 257 + c] = src[c];
    }
    __syncthreads();

    const int b   = nb >> 10;
    const int hw0 = nb & (HW - 1);
    const int cg  = tid >> 5;
    #pragma unroll
    for (int c = cg; c < CDIM; c += 8)
        out[b * (CDIM * HW) + c * HW + hw0 + lane] = tile[lane * 257 + c];
}

// ---------------------------------------------------------------------------
extern "C" void kernel_launch(void* const* d_in, const int* in_sizes, int n_in,
                              void* d_out, int out_size) {
    const float* z   = (const float*)d_in[0];   // [16,256,32,32] fp32
    const float* emb = (const float*)d_in[1];   // [8192,256] fp32
    float* out = (float*)d_out;

    cudaFuncSetAttribute(k_main, cudaFuncAttributeMaxDynamicSharedMemorySize,
                         131072);

    k_prep_z<<<dim3(CDIM / 32, HW / 32, BD), dim3(32, 8)>>>(z);
    k_prep_e<<<(KCOD * CDIM) / 256, 256>>>(emb);
    k_ehalf <<<KCOD / 8, 256>>>(emb);
    k_main  <<<NTOT / 128, 256, 131072>>>();
    k_gather<<<NTOT / 32, 256>>>(emb, out);
}

// round 12
// speedup vs baseline: 3.4647x; 1.7175x over previous
#include <cuda_runtime.h>
#include <stdint.h>

#define NTOT  16384      // B*H*W query rows
#define CDIM  256
#define KCOD  8192
#define HW    1024
#define BD    16
#define NCHUNK 8         // K=256 / 32
#define NTILE  64        // KCOD / 128
#define TOTSTEP (NTILE * NCHUNK)   // 512
#define CAP    128       // candidate slots per row
#define MARGIN 1.0f

// ---- device scratch ----
__device__ float g_Ahi[(size_t)NTOT * CDIM];  // 16MB [n][256] tf32-hi, frag-permuted
__device__ float g_Bhi[(size_t)KCOD * CDIM];  //  8MB [k][256] tf32-hi, frag-permuted
__device__ float g_zf [(size_t)NTOT * CDIM];  // 16MB plain fp32 z rows (rescore)
__device__ float g_eh [KCOD];                 // 0.5*||e||^2
__device__ int   g_cand[(size_t)NTOT * CAP];  // 8MB candidate code ids
__device__ int   g_cnt [NTOT];
__device__ int   g_idx [NTOT];

// ---------------------------------------------------------------------------
__device__ __forceinline__ uint32_t smem_u32(const void* p) {
    uint32_t a;
    asm("{ .reg .u64 t; cvta.to.shared.u64 t, %1; cvt.u32.u64 %0, t; }"
        : "=r"(a) : "l"(p));
    return a;
}
__device__ __forceinline__ float to_tf32(float x) {
    float r;
    asm("cvt.rna.tf32.f32 %0, %1;" : "=f"(r) : "f"(x));
    return r;
}
__device__ __forceinline__ void cpa16(uint32_t s, const void* g) {
    asm volatile("cp.async.cg.shared.global [%0], [%1], 16;"
                 :: "r"(s), "l"(g) : "memory");
}
// fragment slot permutation within each k8 group: slot = 2*(k&3) + (k>>2)
__device__ __forceinline__ int slot_of(int u) {
    return (u & ~7) | (((u & 3) << 1) | ((u >> 2) & 1));
}
__device__ __forceinline__ void mma8(float* d, float a0, float a1, float a2,
                                     float a3, float b0, float b1) {
    asm volatile(
        "mma.sync.aligned.m16n8k8.row.col.f32.tf32.tf32.f32 "
        "{%0,%1,%2,%3},{%4,%5,%6,%7},{%8,%9},{%0,%1,%2,%3};"
        : "+f"(d[0]), "+f"(d[1]), "+f"(d[2]), "+f"(d[3])
        : "r"(__float_as_uint(a0)), "r"(__float_as_uint(a1)),
          "r"(__float_as_uint(a2)), "r"(__float_as_uint(a3)),
          "r"(__float_as_uint(b0)), "r"(__float_as_uint(b1)));
}
// order-preserving float <-> uint for atomicMax
__device__ __forceinline__ uint32_t fkey(float f) {
    uint32_t u = __float_as_uint(f);
    return (u & 0x80000000u) ? ~u : (u | 0x80000000u);
}
__device__ __forceinline__ float funkey(uint32_t k) {
    return (k & 0x80000000u) ? __uint_as_float(k & 0x7fffffffu)
                             : __uint_as_float(~k);
}

// ---------------------------------------------------------------------------
// Prep: z [B,C,HW] -> g_Ahi (tf32 hi, frag-permuted) + g_zf (plain fp32 rows)
// ---------------------------------------------------------------------------
__global__ void k_prep_z(const float* __restrict__ z) {
    __shared__ float t[32][33];
    const int c0 = blockIdx.x * 32, hw0 = blockIdx.y * 32, b = blockIdx.z;
    const int tx = threadIdx.x, ty = threadIdx.y;
    #pragma unroll
    for (int i = 0; i < 32; i += 8)
        t[ty + i][tx] = z[((size_t)b * CDIM + c0 + ty + i) * HW + hw0 + tx];
    __syncthreads();
    #pragma unroll
    for (int i = 0; i < 32; i += 8) {
        float v  = t[tx][ty + i];             // z[c0+tx][hw0+ty+i]
        int   c  = c0 + tx;
        size_t n = (size_t)b * HW + hw0 + ty + i;
        g_zf [n * CDIM + c]          = v;
        g_Ahi[n * CDIM + slot_of(c)] = to_tf32(v);
    }
}

// emb [K,C] -> g_Bhi (tf32 hi, frag-permuted)
__global__ void k_prep_e(const float* __restrict__ emb) {
    int i = blockIdx.x * 256 + threadIdx.x;
    int k = i >> 8, c = i & 255;
    g_Bhi[(size_t)k * CDIM + slot_of(c)] = to_tf32(emb[i]);
}

// g_eh[k] = 0.5*||e_k||^2 (fp32)
__global__ void k_ehalf(const float* __restrict__ emb) {
    int k    = blockIdx.x * (blockDim.x >> 5) + (threadIdx.x >> 5);
    int lane = threadIdx.x & 31;
    const float* row = emb + (size_t)k * CDIM;
    float s = 0.0f;
    #pragma unroll
    for (int c = lane; c < CDIM; c += 32) { float v = row[c]; s = fmaf(v, v, s); }
    #pragma unroll
    for (int off = 16; off; off >>= 1) s += __shfl_xor_sync(0xffffffffu, s, off);
    if (lane == 0) g_eh[k] = 0.5f * s;
}

// ---------------------------------------------------------------------------
// Screen: tf32 hi*hi GEMM (K=256) + margin-based candidate collection.
// CTA: 128 queries x 64 tiles of 128 codes, 8 warps (warp tile 32x64).
// 4-stage cp.async ring (4 x 32KB), XOR-swizzled conflict-free LDS.64.
// |approx - exact| <= ~0.18 deterministic; MARGIN=1.0 guarantees the exact
// winner lands in the candidate list (superset: threshold uses running max).
// ---------------------------------------------------------------------------
__global__ __launch_bounds__(256, 1) void k_screen() {
    extern __shared__ float sm[];   // 4*8192 stage floats | eh_s[128] | s_best[128]
    float*    eh_s   = sm + 32768;
    uint32_t* s_best = (uint32_t*)(sm + 32768 + 128);

    const int tid  = threadIdx.x;
    const int lane = tid & 31, wid = tid >> 5;
    const int wm = wid & 3, wn = wid >> 2;
    const int g = lane >> 2, tig = lane & 3;
    const int tig2 = tig >> 1, tig1 = tig & 1;
    const int m0 = blockIdx.x * 128;
    const uint32_t smb = smem_u32(sm);

    // init per-row running max + global candidate counters (rows are CTA-private)
    if (tid < 128) {
        s_best[tid] = fkey(-3.0e38f);
        g_cnt[m0 + tid] = 0;
    }
    __syncthreads();

    float acc[2][8][4];

    auto issue = [&](int s) {
        int tile = s >> 3, chunk = s & 7;
        int u0 = chunk * 32;
        uint32_t stg = smb + (uint32_t)(s & 3) * 32768u;
        const float* Ag = g_Ahi + (size_t)m0 * CDIM + u0;
        const float* Bg = g_Bhi + (size_t)(tile * 128) * CDIM + u0;
        #pragma unroll
        for (int it = 0; it < 4; ++it) {
            int cidx = it * 256 + tid;
            int row = cidx >> 3, lc = cidx & 7;
            uint32_t d = stg + (uint32_t)row * 128u +
                         (uint32_t)((lc ^ ((row & 3) << 1)) << 4);
            cpa16(d,          Ag + (size_t)row * CDIM + lc * 4);
            cpa16(d + 16384u, Bg + (size_t)row * CDIM + lc * 4);
        }
    };
    auto ldp = [&](const float* base, int row, int l) -> float2 {
        int pc = (2 * l + tig2) ^ ((row & 3) << 1);
        return *(const float2*)(base + row * 32 + pc * 4 + tig1 * 2);
    };

    issue(0); asm volatile("cp.async.commit_group;" ::: "memory");
    issue(1); asm volatile("cp.async.commit_group;" ::: "memory");

    for (int s = 0; s < TOTSTEP; ++s) {
        const int tile = s >> 3;
        const int chunk = s & 7;
        if (chunk == 0) {
            #pragma unroll
            for (int mi = 0; mi < 2; mi++)
                #pragma unroll
                for (int ni = 0; ni < 8; ni++)
                    #pragma unroll
                    for (int r = 0; r < 4; r++) acc[mi][ni][r] = 0.0f;
        }
        if (s + 2 < TOTSTEP) issue(s + 2);
        asm volatile("cp.async.commit_group;" ::: "memory");
        asm volatile("cp.async.wait_group 2;" ::: "memory");
        __syncthreads();

        if (chunk == 0 && tid < 128)       // eh for this tile (guarded by syncs)
            eh_s[tid] = g_eh[tile * 128 + tid];

        const float* stA = sm + (s & 3) * 8192;
        const float* stB = stA + 4096;
        #pragma unroll
        for (int l = 0; l < 4; ++l) {
            float2 fa[2][2];
            #pragma unroll
            for (int mi = 0; mi < 2; ++mi) {
                int r0 = wm * 32 + mi * 16 + g;
                fa[mi][0] = ldp(stA, r0, l);
                fa[mi][1] = ldp(stA, r0 + 8, l);
            }
            float2 fb[8];
            #pragma unroll
            for (int ni = 0; ni < 8; ++ni)
                fb[ni] = ldp(stB, wn * 64 + ni * 8 + g, l);
            #pragma unroll
            for (int mi = 0; mi < 2; ++mi)
                #pragma unroll
                for (int ni = 0; ni < 8; ++ni)
                    mma8(acc[mi][ni], fa[mi][0].x, fa[mi][1].x,
                         fa[mi][0].y, fa[mi][1].y, fb[ni].x, fb[ni].y);
        }

        if (chunk == 7) {
            // collection epilogue: approx score = acc - 0.5||e||^2
            const int k0 = tile * 128;
            float lb[2][2];
            #pragma unroll
            for (int mi = 0; mi < 2; ++mi)
                #pragma unroll
                for (int h = 0; h < 2; ++h)
                    lb[mi][h] = funkey(s_best[wm * 32 + mi * 16 + g + 8 * h]);

            #pragma unroll
            for (int ni = 0; ni < 8; ++ni) {
                #pragma unroll
                for (int r = 0; r < 4; ++r) {
                    const int lc  = wn * 64 + ni * 8 + 2 * tig + (r & 1);
                    const float e = eh_s[lc];
                    const int h   = r >> 1;
                    #pragma unroll
                    for (int mi = 0; mi < 2; ++mi) {
                        float v = acc[mi][ni][r] - e;
                        if (v > lb[mi][h] - MARGIN) {
                            int rl  = wm * 32 + mi * 16 + g + 8 * h;
                            int row = m0 + rl;
                            int pos = atomicAdd(&g_cnt[row], 1);
                            if (pos < CAP) g_cand[(size_t)row * CAP + pos] = k0 + lc;
                            if (v > lb[mi][h]) {
                                lb[mi][h] = v;
                                atomicMax(&s_best[rl], fkey(v));
                            }
                        }
                    }
                }
            }
        }
    }
}

// ---------------------------------------------------------------------------
// Rescore: exact fp32 score for each candidate; one warp per query row.
// Max with lowest-index tie-break is order-independent -> deterministic.
// ---------------------------------------------------------------------------
__global__ void k_rescore(const float* __restrict__ emb) {
    const int wid  = threadIdx.x >> 5;
    const int lane = threadIdx.x & 31;
    const int row  = blockIdx.x * 8 + wid;

    int cnt = g_cnt[row];
    if (cnt > CAP) cnt = CAP;

    const float* zr = g_zf + (size_t)row * CDIM;
    float zc[8];
    #pragma unroll
    for (int i = 0; i < 8; ++i) zc[i] = zr[lane + 32 * i];

    float best = -3.0e38f;
    int   bidx = 0x7fffffff;
    for (int j = 0; j < cnt; ++j) {
        int idx = g_cand[(size_t)row * CAP + j];
        const float* er = emb + (size_t)idx * CDIM;
        float s = 0.0f;
        #pragma unroll
        for (int i = 0; i < 8; ++i) s = fmaf(zc[i], er[lane + 32 * i], s);
        #pragma unroll
        for (int off = 16; off; off >>= 1) s += __shfl_xor_sync(0xffffffffu, s, off);
        s -= g_eh[idx];
        if (s > best || (s == best && idx < bidx)) { best = s; bidx = idx; }
    }
    if (lane == 0) g_idx[row] = bidx;
}

// ---------------------------------------------------------------------------
// Gather: out[b][c][hw] = emb[idx[b*HW+hw]][c].
// ---------------------------------------------------------------------------
__global__ void k_gather(const float* __restrict__ emb, float* __restrict__ out) {
    __shared__ float tile[32 * 257];
    __shared__ int   sidx[32];
    const int nb  = blockIdx.x * 32;
    const int tid = threadIdx.x;
    if (tid < 32) sidx[tid] = g_idx[nb + tid];
    __syncthreads();

    const int w = tid >> 5, lane = tid & 31;
    #pragma unroll
    for (int r = w * 4; r < w * 4 + 4; ++r) {
        const float* src = emb + (size_t)sidx[r] * CDIM;
        #pragma unroll
        for (int c = lane; c < CDIM; c += 32)
            tile[r * 257 + c] = src[c];
    }
    __syncthreads();

    const int b   = nb >> 10;
    const int hw0 = nb & (HW - 1);
    const int cg  = tid >> 5;
    #pragma unroll
    for (int c = cg; c < CDIM; c += 8)
        out[b * (CDIM * HW) + c * HW + hw0 + lane] = tile[lane * 257 + c];
}

// ---------------------------------------------------------------------------
extern "C" void kernel_launch(void* const* d_in, const int* in_sizes, int n_in,
                              void* d_out, int out_size) {
    const float* z   = (const float*)d_in[0];   // [16,256,32,32] fp32
    const float* emb = (const float*)d_in[1];   // [8192,256] fp32
    float* out = (float*)d_out;

    cudaFuncSetAttribute(k_screen, cudaFuncAttributeMaxDynamicSharedMemorySize,
                         132096);

    k_prep_z <<<dim3(CDIM / 32, HW / 32, BD), dim3(32, 8)>>>(z);
    k_prep_e <<<(KCOD * CDIM) / 256, 256>>>(emb);
    k_ehalf  <<<KCOD / 8, 256>>>(emb);
    k_screen <<<NTOT / 128, 256, 132096>>>();
    k_rescore<<<NTOT / 8, 256>>>(emb);
    k_gather <<<NTOT / 32, 256>>>(emb, out);
}

// round 15
// speedup vs baseline: 5.0724x; 1.4640x over previous
#include <cuda_runtime.h>
#include <cuda_bf16.h>
#include <stdint.h>

#define NTOT  16384      // B*H*W query rows
#define CDIM  256
#define HW    1024
#define BD    16
#define KCOD  8192
#define NCHUNK 4         // K=256 bf16 / 64 per chunk
#define NTILE  64        // KCOD / 128
#define TOTSTEP (NTILE * NCHUNK)   // 256
#define CAP    192       // candidate slots per row
#define MARGIN 2.0f      // > 2 * worst-case bf16 screen error (0.64)

// ---- device scratch ----
__device__ uint32_t g_Abf[(size_t)NTOT * 128];  // 8MB [n][128 words] bf16x2, perm
__device__ uint32_t g_Bbf[(size_t)KCOD * 128];  // 4MB [k][128 words] bf16x2, perm
__device__ float    g_zf [(size_t)NTOT * CDIM]; // 16MB plain fp32 z rows (rescore)
__device__ float    g_eh [KCOD];                // 0.5*||e||^2
__device__ int      g_cand[(size_t)NTOT * CAP];
__device__ int      g_cnt [NTOT];
__device__ int      g_idx [NTOT];

// ---------------------------------------------------------------------------
__device__ __forceinline__ uint32_t smem_u32(const void* p) {
    uint32_t a;
    asm("{ .reg .u64 t; cvta.to.shared.u64 t, %1; cvt.u32.u64 %0, t; }"
        : "=r"(a) : "l"(p));
    return a;
}
__device__ __forceinline__ void cpa16(uint32_t s, const void* g) {
    asm volatile("cp.async.cg.shared.global [%0], [%1], 16;"
                 :: "r"(s), "l"(g) : "memory");
}
// b32-word permutation within each k16 group: slot = 2*(u&3) + (u>>2)
// -> thread tig's word pair (u=tig, u=tig+4) becomes adjacent (LDS.64).
__device__ __forceinline__ int wperm(int u) { return 2 * (u & 3) + (u >> 2); }

__device__ __forceinline__ void mma16(float* d, uint32_t a0, uint32_t a1,
                                      uint32_t a2, uint32_t a3,
                                      uint32_t b0, uint32_t b1) {
    asm volatile(
        "mma.sync.aligned.m16n8k16.row.col.f32.bf16.bf16.f32 "
        "{%0,%1,%2,%3},{%4,%5,%6,%7},{%8,%9},{%0,%1,%2,%3};"
        : "+f"(d[0]), "+f"(d[1]), "+f"(d[2]), "+f"(d[3])
        : "r"(a0), "r"(a1), "r"(a2), "r"(a3), "r"(b0), "r"(b1));
}
// order-preserving float <-> uint for atomicMax
__device__ __forceinline__ uint32_t fkey(float f) {
    uint32_t u = __float_as_uint(f);
    return (u & 0x80000000u) ? ~u : (u | 0x80000000u);
}
__device__ __forceinline__ float funkey(uint32_t k) {
    return (k & 0x80000000u) ? __uint_as_float(k & 0x7fffffffu)
                             : __uint_as_float(~k);
}
// half-index (bf16 granularity) for channel c within a 256-ch permuted row
__device__ __forceinline__ int half_slot(int c) {
    int u = (c >> 1) & 7;                       // word within k16 group
    return ((c >> 4) << 4) + wperm(u) * 2 + (c & 1);
}

// ---------------------------------------------------------------------------
// Prep: z [B,C,HW] -> g_Abf (bf16 permuted) + g_zf (plain fp32 rows)
// ---------------------------------------------------------------------------
__global__ void k_prep_z(const float* __restrict__ z) {
    __shared__ float t[32][33];
    const int c0 = blockIdx.x * 32, hw0 = blockIdx.y * 32, b = blockIdx.z;
    const int tx = threadIdx.x, ty = threadIdx.y;
    #pragma unroll
    for (int i = 0; i < 32; i += 8)
        t[ty + i][tx] = z[((size_t)b * CDIM + c0 + ty + i) * HW + hw0 + tx];
    __syncthreads();
    #pragma unroll
    for (int i = 0; i < 32; i += 8) {
        float v  = t[tx][ty + i];             // z[c0+tx][hw0+ty+i]
        int   c  = c0 + tx;
        size_t n = (size_t)b * HW + hw0 + ty + i;
        g_zf[n * CDIM + c] = v;
        ((__nv_bfloat16*)g_Abf)[n * 256 + half_slot(c)] = __float2bfloat16_rn(v);
    }
}

// emb [K,C] -> g_Bbf (bf16 permuted)
__global__ void k_prep_e(const float* __restrict__ emb) {
    int i = blockIdx.x * 256 + threadIdx.x;
    int k = i >> 8, c = i & 255;
    ((__nv_bfloat16*)g_Bbf)[(size_t)k * 256 + half_slot(c)] =
        __float2bfloat16_rn(emb[i]);
}

// g_eh[k] = 0.5*||e_k||^2 (fp32)
__global__ void k_ehalf(const float* __restrict__ emb) {
    int k    = blockIdx.x * (blockDim.x >> 5) + (threadIdx.x >> 5);
    int lane = threadIdx.x & 31;
    const float* row = emb + (size_t)k * CDIM;
    float s = 0.0f;
    #pragma unroll
    for (int c = lane; c < CDIM; c += 32) { float v = row[c]; s = fmaf(v, v, s); }
    #pragma unroll
    for (int off = 16; off; off >>= 1) s += __shfl_xor_sync(0xffffffffu, s, off);
    if (lane == 0) g_eh[k] = 0.5f * s;
}

// ---------------------------------------------------------------------------
// Screen: bf16 m16n8k16 GEMM (K=256) + margin candidate collection.
// CTA: 128 queries x 64 tiles of 128 codes, 8 warps (warp tile 32x64).
// 4-stage cp.async ring (4 x 32KB), XOR-swizzled conflict-free LDS.64.
// Chunk = 64 k-elements (128B/row) -> 256 steps total.
// ---------------------------------------------------------------------------
__global__ __launch_bounds__(256, 1) void k_screen() {
    extern __shared__ float sm[];   // 4*8192 stage floats | eh_s[128] | s_best[128]
    float*    eh_s   = sm + 32768;
    uint32_t* s_best = (uint32_t*)(sm + 32768 + 128);

    const int tid  = threadIdx.x;
    const int lane = tid & 31, wid = tid >> 5;
    const int wm = wid & 3, wn = wid >> 2;
    const int g = lane >> 2, tig = lane & 3;
    const int tig2 = tig >> 1, tig1 = tig & 1;
    const int m0 = blockIdx.x * 128;
    const uint32_t smb = smem_u32(sm);

    if (tid < 128) {
        s_best[tid] = fkey(-3.0e38f);
        g_cnt[m0 + tid] = 0;      // rows are CTA-private
    }
    __syncthreads();

    float acc[2][8][4];

    auto issue = [&](int s) {
        int tile = s >> 2, chunk = s & 3;
        int u0 = chunk * 32;                       // word offset within row
        uint32_t stg = smb + (uint32_t)(s & 3) * 32768u;
        const uint32_t* Ag = g_Abf + (size_t)m0 * 128 + u0;
        const uint32_t* Bg = g_Bbf + (size_t)(tile * 128) * 128 + u0;
        #pragma unroll
        for (int it = 0; it < 4; ++it) {
            int cidx = it * 256 + tid;
            int row = cidx >> 3, lc = cidx & 7;    // 8 x 16B chunks per row
            uint32_t d = stg + (uint32_t)row * 128u +
                         (uint32_t)((lc ^ ((row & 3) << 1)) << 4);
            cpa16(d,          Ag + (size_t)row * 128 + lc * 4);
            cpa16(d + 16384u, Bg + (size_t)row * 128 + lc * 4);
        }
    };
    // fragment word-pair load (LDS.64, conflict-free): l = k16 group 0..3
    auto ldp = [&](const float* base, int row, int l) -> float2 {
        int pc = (2 * l + tig2) ^ ((row & 3) << 1);
        return *(const float2*)(base + row * 32 + pc * 4 + tig1 * 2);
    };

    issue(0); asm volatile("cp.async.commit_group;" ::: "memory");
    issue(1); asm volatile("cp.async.commit_group;" ::: "memory");

    for (int s = 0; s < TOTSTEP; ++s) {
        const int tile = s >> 2;
        const int chunk = s & 3;
        if (chunk == 0) {
            #pragma unroll
            for (int mi = 0; mi < 2; mi++)
                #pragma unroll
                for (int ni = 0; ni < 8; ni++)
                    #pragma unroll
                    for (int r = 0; r < 4; r++) acc[mi][ni][r] = 0.0f;
        }
        if (s + 2 < TOTSTEP) issue(s + 2);
        asm volatile("cp.async.commit_group;" ::: "memory");
        asm volatile("cp.async.wait_group 2;" ::: "memory");
        __syncthreads();

        if (chunk == 0 && tid < 128)
            eh_s[tid] = g_eh[tile * 128 + tid];

        const float* stA = sm + (s & 3) * 8192;
        const float* stB = stA + 4096;
        #pragma unroll
        for (int l = 0; l < 4; ++l) {             // 4 k16 groups per chunk
            float2 fa[2][2];
            #pragma unroll
            for (int mi = 0; mi < 2; ++mi) {
                int r0 = wm * 32 + mi * 16 + g;
                fa[mi][0] = ldp(stA, r0, l);       // (a0, a2)
                fa[mi][1] = ldp(stA, r0 + 8, l);   // (a1, a3)
            }
            float2 fb[8];
            #pragma unroll
            for (int ni = 0; ni < 8; ++ni)
                fb[ni] = ldp(stB, wn * 64 + ni * 8 + g, l);   // (b0, b1)
            #pragma unroll
            for (int mi = 0; mi < 2; ++mi)
                #pragma unroll
                for (int ni = 0; ni < 8; ++ni)
                    mma16(acc[mi][ni],
                          __float_as_uint(fa[mi][0].x), __float_as_uint(fa[mi][1].x),
                          __float_as_uint(fa[mi][0].y), __float_as_uint(fa[mi][1].y),
                          __float_as_uint(fb[ni].x),    __float_as_uint(fb[ni].y));
        }

        if (chunk == 3) {
            // collection epilogue: approx score = acc - 0.5||e||^2
            const int k0 = tile * 128;
            float lb[2][2];
            #pragma unroll
            for (int mi = 0; mi < 2; ++mi)
                #pragma unroll
                for (int h = 0; h < 2; ++h)
                    lb[mi][h] = funkey(s_best[wm * 32 + mi * 16 + g + 8 * h]);

            #pragma unroll
            for (int ni = 0; ni < 8; ++ni) {
                #pragma unroll
                for (int r = 0; r < 4; ++r) {
                    const int lc  = wn * 64 + ni * 8 + 2 * tig + (r & 1);
                    const float e = eh_s[lc];
                    const int h   = r >> 1;
                    #pragma unroll
                    for (int mi = 0; mi < 2; ++mi) {
                        float v = acc[mi][ni][r] - e;
                        if (v > lb[mi][h] - MARGIN) {
                            int rl  = wm * 32 + mi * 16 + g + 8 * h;
                            int row = m0 + rl;
                            int pos = atomicAdd(&g_cnt[row], 1);
                            if (pos < CAP) g_cand[(size_t)row * CAP + pos] = k0 + lc;
                            if (v > lb[mi][h]) {
                                lb[mi][h] = v;
                                atomicMax(&s_best[rl], fkey(v));
                            }
                        }
                    }
                }
            }
        }
    }
}

// ---------------------------------------------------------------------------
// Rescore: exact fp32 score for each candidate; one warp per query row.
// Max with lowest-index tie-break is order-independent -> deterministic.
// ---------------------------------------------------------------------------
__global__ void k_rescore(const float* __restrict__ emb) {
    const int wid  = threadIdx.x >> 5;
    const int lane = threadIdx.x & 31;
    const int row  = blockIdx.x * 8 + wid;

    int cnt = g_cnt[row];
    if (cnt > CAP) cnt = CAP;

    const float* zr = g_zf + (size_t)row * CDIM;
    float zc[8];
    #pragma unroll
    for (int i = 0; i < 8; ++i) zc[i] = zr[lane + 32 * i];

    float best = -3.0e38f;
    int   bidx = 0x7fffffff;
    for (int j = 0; j < cnt; ++j) {
        int idx = g_cand[(size_t)row * CAP + j];
        const float* er = emb + (size_t)idx * CDIM;
        float s = 0.0f;
        #pragma unroll
        for (int i = 0; i < 8; ++i) s = fmaf(zc[i], er[lane + 32 * i], s);
        #pragma unroll
        for (int off = 16; off; off >>= 1) s += __shfl_xor_sync(0xffffffffu, s, off);
        s -= g_eh[idx];
        if (s > best || (s == best && idx < bidx)) { best = s; bidx = idx; }
    }
    if (lane == 0) g_idx[row] = bidx;
}

// ---------------------------------------------------------------------------
// Gather: out[b][c][hw] = emb[idx[b*HW+hw]][c].
// ---------------------------------------------------------------------------
__global__ void k_gather(const float* __restrict__ emb, float* __restrict__ out) {
    __shared__ float tile[32 * 257];
    __shared__ int   sidx[32];
    const int nb  = blockIdx.x * 32;
    const int tid = threadIdx.x;
    if (tid < 32) sidx[tid] = g_idx[nb + tid];
    __syncthreads();

    const int w = tid >> 5, lane = tid & 31;
    #pragma unroll
    for (int r = w * 4; r < w * 4 + 4; ++r) {
        const float* src = emb + (size_t)sidx[r] * CDIM;
        #pragma unroll
        for (int c = lane; c < CDIM; c += 32)
            tile[r * 257 + c] = src[c];
    }
    __syncthreads();

    const int b   = nb >> 10;
    const int hw0 = nb & (HW - 1);
    const int cg  = tid >> 5;
    #pragma unroll
    for (int c = cg; c < CDIM; c += 8)
        out[b * (CDIM * HW) + c * HW + hw0 + lane] = tile[lane * 257 + c];
}

// ---------------------------------------------------------------------------
extern "C" void kernel_launch(void* const* d_in, const int* in_sizes, int n_in,
                              void* d_out, int out_size) {
    const float* z   = (const float*)d_in[0];   // [16,256,32,32] fp32
    const float* emb = (const float*)d_in[1];   // [8192,256] fp32
    float* out = (float*)d_out;

    cudaFuncSetAttribute(k_screen, cudaFuncAttributeMaxDynamicSharedMemorySize,
                         132096);

    k_prep_z <<<dim3(CDIM / 32, HW / 32, BD), dim3(32, 8)>>>(z);
    k_prep_e <<<(KCOD * CDIM) / 256, 256>>>(emb);
    k_ehalf  <<<KCOD / 8, 256>>>(emb);
    k_screen <<<NTOT / 128, 256, 132096>>>();
    k_rescore<<<NTOT / 8, 256>>>(emb);
    k_gather <<<NTOT / 32, 256>>>(emb, out);
}

// round 16
// speedup vs baseline: 5.9983x; 1.1825x over previous
#include <cuda_runtime.h>
#include <cuda_bf16.h>
#include <stdint.h>

#define NTOT  16384      // B*H*W query rows
#define CDIM  256
#define HW    1024
#define BD    16
#define KCOD  8192
#define NTILE 64         // KCOD / 128
#define CAP   192        // candidate slots per row
#define MARGIN 2.0f      // > 2 * worst-case bf16 screen error (~0.64)

// smem float offsets
#define SM_A    0        // A panel: 128 rows * 128 floats (512B/row) = 64KB
#define SM_B0   16384    // B stage 0: 64KB
#define SM_B1   32768    // B stage 1: 64KB
#define SM_BEST 49152    // uint32 s_best[128]
#define SMEM_TOTAL (49152 * 4 + 512)   // 197120 B

// ---- device scratch ----
__device__ uint32_t g_Abf[(size_t)NTOT * 128];  // 8MB [n][128 words] bf16x2, perm
__device__ uint32_t g_Bbf[(size_t)KCOD * 128];  // 4MB [k][128 words] bf16x2, perm
__device__ float    g_zf [(size_t)NTOT * CDIM]; // 16MB plain fp32 z rows (rescore)
__device__ float    g_eh [KCOD];                // 0.5*||e||^2
__device__ int      g_cand[(size_t)NTOT * CAP];
__device__ int      g_cnt [NTOT];
__device__ int      g_idx [NTOT];

// ---------------------------------------------------------------------------
__device__ __forceinline__ uint32_t smem_u32(const void* p) {
    uint32_t a;
    asm("{ .reg .u64 t; cvta.to.shared.u64 t, %1; cvt.u32.u64 %0, t; }"
        : "=r"(a) : "l"(p));
    return a;
}
__device__ __forceinline__ void cpa16(uint32_t s, const void* g) {
    asm volatile("cp.async.cg.shared.global [%0], [%1], 16;"
                 :: "r"(s), "l"(g) : "memory");
}
// b32-word permutation within each k16 group: slot = 2*(u&3) + (u>>2)
__device__ __forceinline__ int wperm(int u) { return 2 * (u & 3) + (u >> 2); }

__device__ __forceinline__ void mma16(float* d, uint32_t a0, uint32_t a1,
                                      uint32_t a2, uint32_t a3,
                                      uint32_t b0, uint32_t b1) {
    asm volatile(
        "mma.sync.aligned.m16n8k16.row.col.f32.bf16.bf16.f32 "
        "{%0,%1,%2,%3},{%4,%5,%6,%7},{%8,%9},{%0,%1,%2,%3};"
        : "+f"(d[0]), "+f"(d[1]), "+f"(d[2]), "+f"(d[3])
        : "r"(a0), "r"(a1), "r"(a2), "r"(a3), "r"(b0), "r"(b1));
}
// order-preserving float <-> uint for atomicMax
__device__ __forceinline__ uint32_t fkey(float f) {
    uint32_t u = __float_as_uint(f);
    return (u & 0x80000000u) ? ~u : (u | 0x80000000u);
}
__device__ __forceinline__ float funkey(uint32_t k) {
    return (k & 0x80000000u) ? __uint_as_float(k & 0x7fffffffu)
                             : __uint_as_float(~k);
}
// half-index (bf16 granularity) for channel c within a 256-ch permuted row
__device__ __forceinline__ int half_slot(int c) {
    int u = (c >> 1) & 7;
    return ((c >> 4) << 4) + wperm(u) * 2 + (c & 1);
}

// ---------------------------------------------------------------------------
// Prep: z [B,C,HW] -> g_Abf (bf16 permuted) + g_zf (plain fp32 rows)
// ---------------------------------------------------------------------------
__global__ void k_prep_z(const float* __restrict__ z) {
    __shared__ float t[32][33];
    const int c0 = blockIdx.x * 32, hw0 = blockIdx.y * 32, b = blockIdx.z;
    const int tx = threadIdx.x, ty = threadIdx.y;
    #pragma unroll
    for (int i = 0; i < 32; i += 8)
        t[ty + i][tx] = z[((size_t)b * CDIM + c0 + ty + i) * HW + hw0 + tx];
    __syncthreads();
    #pragma unroll
    for (int i = 0; i < 32; i += 8) {
        float v  = t[tx][ty + i];
        int   c  = c0 + tx;
        size_t n = (size_t)b * HW + hw0 + ty + i;
        g_zf[n * CDIM + c] = v;
        ((__nv_bfloat16*)g_Abf)[n * 256 + half_slot(c)] = __float2bfloat16_rn(v);
    }
}

// emb [K,C] -> g_Bbf (bf16 permuted)
__global__ void k_prep_e(const float* __restrict__ emb) {
    int i = blockIdx.x * 256 + threadIdx.x;
    int k = i >> 8, c = i & 255;
    ((__nv_bfloat16*)g_Bbf)[(size_t)k * 256 + half_slot(c)] =
        __float2bfloat16_rn(emb[i]);
}

// g_eh[k] = 0.5*||e_k||^2 (fp32)
__global__ void k_ehalf(const float* __restrict__ emb) {
    int k    = blockIdx.x * (blockDim.x >> 5) + (threadIdx.x >> 5);
    int lane = threadIdx.x & 31;
    const float* row = emb + (size_t)k * CDIM;
    float s = 0.0f;
    #pragma unroll
    for (int c = lane; c < CDIM; c += 32) { float v = row[c]; s = fmaf(v, v, s); }
    #pragma unroll
    for (int off = 16; off; off >>= 1) s += __shfl_xor_sync(0xffffffffu, s, off);
    if (lane == 0) g_eh[k] = 0.5f * s;
}

// ---------------------------------------------------------------------------
// Screen: bf16 m16n8k16 GEMM (K=256) + margin candidate collection.
// A panel (128 rows x 256 bf16 = 64KB) resident in smem for the whole kernel;
// B tiles (128 codes x 256 bf16 = 64KB) streamed through a 2-deep cp.async
// ring. One wait + one __syncthreads per 128-code tile (64 steps total).
// Row layout: 4 x 128B chunks, word-permuted + XOR-swizzled (conflict-free
// LDS.64 fragment loads, same scheme as validated in R11-R15).
// ---------------------------------------------------------------------------
__global__ __launch_bounds__(256, 1) void k_screen() {
    extern __shared__ float sm[];
    uint32_t* s_best = (uint32_t*)(sm + SM_BEST);

    const int tid  = threadIdx.x;
    const int lane = tid & 31, wid = tid >> 5;
    const int wm = wid & 3, wn = wid >> 2;
    const int g = lane >> 2, tig = lane & 3;
    const int tig2 = tig >> 1, tig1 = tig & 1;
    const int m0 = blockIdx.x * 128;
    const uint32_t smb = smem_u32(sm);

    if (tid < 128) {
        s_best[tid] = fkey(-3.0e38f);
        g_cnt[m0 + tid] = 0;      // rows are CTA-private
    }

    // ---- fill resident A panel: 128 rows x 32 16B-units ----
    #pragma unroll
    for (int it = 0; it < 16; ++it) {
        int cidx = it * 256 + tid;
        int row = cidx >> 5, u = cidx & 31;
        int chunk = u >> 3, lc = u & 7;
        uint32_t d = smb + (uint32_t)row * 512u + (uint32_t)chunk * 128u +
                     (uint32_t)((lc ^ ((row & 3) << 1)) << 4);
        cpa16(d, g_Abf + (size_t)(m0 + row) * 128 + u * 4);
    }
    // ---- B tile loader ----
    auto issueB = [&](int tile, int stg) {
        uint32_t base = smb + (uint32_t)(SM_B0 * 4) + (uint32_t)stg * 65536u;
        const uint32_t* Bg = g_Bbf + (size_t)(tile * 128) * 128;
        #pragma unroll
        for (int it = 0; it < 16; ++it) {
            int cidx = it * 256 + tid;
            int row = cidx >> 5, u = cidx & 31;
            int chunk = u >> 3, lc = u & 7;
            uint32_t d = base + (uint32_t)row * 512u + (uint32_t)chunk * 128u +
                         (uint32_t)((lc ^ ((row & 3) << 1)) << 4);
            cpa16(d, Bg + (size_t)row * 128 + u * 4);
        }
    };
    issueB(0, 0);
    asm volatile("cp.async.commit_group;" ::: "memory");
    asm volatile("cp.async.wait_group 0;" ::: "memory");
    __syncthreads();

    // fragment word-pair load; l = k16 group 0..15, row stride 128 floats
    auto ldp = [&](const float* base, int row, int l) -> float2 {
        int chunk = l >> 2, lw = l & 3;
        int pc = (2 * lw + tig2) ^ ((row & 3) << 1);
        return *(const float2*)(base + row * 128 + chunk * 32 + pc * 4 + tig1 * 2);
    };

    for (int t = 0; t < NTILE; ++t) {
        if (t + 1 < NTILE) {
            issueB(t + 1, (t + 1) & 1);
            asm volatile("cp.async.commit_group;" ::: "memory");
        }

        const float* stB = sm + ((t & 1) ? SM_B1 : SM_B0);
        float acc[2][8][4];
        #pragma unroll
        for (int mi = 0; mi < 2; mi++)
            #pragma unroll
            for (int ni = 0; ni < 8; ni++)
                #pragma unroll
                for (int r = 0; r < 4; r++) acc[mi][ni][r] = 0.0f;

        #pragma unroll
        for (int l = 0; l < 16; ++l) {
            float2 fa[2][2];
            #pragma unroll
            for (int mi = 0; mi < 2; ++mi) {
                int r0 = wm * 32 + mi * 16 + g;
                fa[mi][0] = ldp(sm, r0, l);        // (a0, a2)
                fa[mi][1] = ldp(sm, r0 + 8, l);    // (a1, a3)
            }
            float2 fb[8];
            #pragma unroll
            for (int ni = 0; ni < 8; ++ni)
                fb[ni] = ldp(stB, wn * 64 + ni * 8 + g, l);   // (b0, b1)
            #pragma unroll
            for (int mi = 0; mi < 2; ++mi)
                #pragma unroll
                for (int ni = 0; ni < 8; ++ni)
                    mma16(acc[mi][ni],
                          __float_as_uint(fa[mi][0].x), __float_as_uint(fa[mi][1].x),
                          __float_as_uint(fa[mi][0].y), __float_as_uint(fa[mi][1].y),
                          __float_as_uint(fb[ni].x),    __float_as_uint(fb[ni].y));
        }

        // collection epilogue: approx score = acc - 0.5||e||^2
        {
            const int k0 = t * 128;
            float lb[2][2];
            #pragma unroll
            for (int mi = 0; mi < 2; ++mi)
                #pragma unroll
                for (int h = 0; h < 2; ++h)
                    lb[mi][h] = funkey(s_best[wm * 32 + mi * 16 + g + 8 * h]);

            #pragma unroll
            for (int ni = 0; ni < 8; ++ni) {
                #pragma unroll
                for (int r = 0; r < 4; ++r) {
                    const int lc  = wn * 64 + ni * 8 + 2 * tig + (r & 1);
                    const float e = __ldg(&g_eh[k0 + lc]);
                    const int h   = r >> 1;
                    #pragma unroll
                    for (int mi = 0; mi < 2; ++mi) {
                        float v = acc[mi][ni][r] - e;
                        if (v > lb[mi][h] - MARGIN) {
                            int rl  = wm * 32 + mi * 16 + g + 8 * h;
                            int row = m0 + rl;
                            int pos = atomicAdd(&g_cnt[row], 1);
                            if (pos < CAP) g_cand[(size_t)row * CAP + pos] = k0 + lc;
                            if (v > lb[mi][h]) {
                                lb[mi][h] = v;
                                atomicMax(&s_best[rl], fkey(v));
                            }
                        }
                    }
                }
            }
        }

        if (t + 1 < NTILE)
            asm volatile("cp.async.wait_group 0;" ::: "memory");
        __syncthreads();
    }
}

// ---------------------------------------------------------------------------
// Rescore: exact fp32 score for each candidate; one warp per query row.
// Max with lowest-index tie-break is order-independent -> deterministic.
// ---------------------------------------------------------------------------
__global__ void k_rescore(const float* __restrict__ emb) {
    const int wid  = threadIdx.x >> 5;
    const int lane = threadIdx.x & 31;
    const int row  = blockIdx.x * 8 + wid;

    int cnt = g_cnt[row];
    if (cnt > CAP) cnt = CAP;

    const float* zr = g_zf + (size_t)row * CDIM;
    float zc[8];
    #pragma unroll
    for (int i = 0; i < 8; ++i) zc[i] = zr[lane + 32 * i];

    float best = -3.0e38f;
    int   bidx = 0x7fffffff;
    for (int j = 0; j < cnt; ++j) {
        int idx = g_cand[(size_t)row * CAP + j];
        const float* er = emb + (size_t)idx * CDIM;
        float s = 0.0f;
        #pragma unroll
        for (int i = 0; i < 8; ++i) s = fmaf(zc[i], er[lane + 32 * i], s);
        #pragma unroll
        for (int off = 16; off; off >>= 1) s += __shfl_xor_sync(0xffffffffu, s, off);
        s -= g_eh[idx];
        if (s > best || (s == best && idx < bidx)) { best = s; bidx = idx; }
    }
    if (lane == 0) g_idx[row] = bidx;
}

// ---------------------------------------------------------------------------
// Gather: out[b][c][hw] = emb[idx[b*HW+hw]][c].
// ---------------------------------------------------------------------------
__global__ void k_gather(const float* __restrict__ emb, float* __restrict__ out) {
    __shared__ float tile[32 * 257];
    __shared__ int   sidx[32];
    const int nb  = blockIdx.x * 32;
    const int tid = threadIdx.x;
    if (tid < 32) sidx[tid] = g_idx[nb + tid];
    __syncthreads();

    const int w = tid >> 5, lane = tid & 31;
    #pragma unroll
    for (int r = w * 4; r < w * 4 + 4; ++r) {
        const float* src = emb + (size_t)sidx[r] * CDIM;
        #pragma unroll
        for (int c = lane; c < CDIM; c += 32)
            tile[r * 257 + c] = src[c];
    }
    __syncthreads();

    const int b   = nb >> 10;
    const int hw0 = nb & (HW - 1);
    const int cg  = tid >> 5;
    #pragma unroll
    for (int c = cg; c < CDIM; c += 8)
        out[b * (CDIM * HW) + c * HW + hw0 + lane] = tile[lane * 257 + c];
}

// ---------------------------------------------------------------------------
extern "C" void kernel_launch(void* const* d_in, const int* in_sizes, int n_in,
                              void* d_out, int out_size) {
    const float* z   = (const float*)d_in[0];   // [16,256,32,32] fp32
    const float* emb = (const float*)d_in[1];   // [8192,256] fp32
    float* out = (float*)d_out;

    cudaFuncSetAttribute(k_screen, cudaFuncAttributeMaxDynamicSharedMemorySize,
                         SMEM_TOTAL);

    k_prep_z <<<dim3(CDIM / 32, HW / 32, BD), dim3(32, 8)>>>(z);
    k_prep_e <<<(KCOD * CDIM) / 256, 256>>>(emb);
    k_ehalf  <<<KCOD / 8, 256>>>(emb);
    k_screen <<<NTOT / 128, 256, SMEM_TOTAL>>>();
    k_rescore<<<NTOT / 8, 256>>>(emb);
    k_gather <<<NTOT / 32, 256>>>(emb, out);
}

// round 17
// speedup vs baseline: 6.9849x; 1.1645x over previous
#include <cuda_runtime.h>
#include <cuda_bf16.h>
#include <stdint.h>

#define NTOT  16384      // B*H*W query rows
#define CDIM  256
#define HW    1024
#define BD    16
#define KCOD  8192
#define NTILE 64         // KCOD / 128
#define CAP   192        // candidate slots per row
#define MARGIN 2.0f      // > 2 * worst-case bf16 screen error (~0.64)

// smem float offsets
#define SM_A    0        // A panel: 128 rows * 128 floats (512B/row) = 64KB
#define SM_B0   16384    // B stage 0: 64KB
#define SM_B1   32768    // B stage 1: 64KB
#define SM_BEST 49152    // uint32 s_best[128]
#define SMEM_TOTAL (49152 * 4 + 512)   // 197120 B

// ---- device scratch ----
__device__ uint32_t g_Abf[(size_t)NTOT * 128];  // 8MB [n][128 words] bf16x2, perm
__device__ uint32_t g_Bbf[(size_t)KCOD * 128];  // 4MB [k][128 words] bf16x2, perm
__device__ float    g_zf [(size_t)NTOT * CDIM]; // 16MB plain fp32 z rows (rescore)
__device__ float    g_eh [KCOD];                // 0.5*||e||^2
__device__ int      g_cand[(size_t)NTOT * CAP];
__device__ int      g_cnt [NTOT];
__device__ int      g_idx [NTOT];

// ---------------------------------------------------------------------------
__device__ __forceinline__ uint32_t smem_u32(const void* p) {
    uint32_t a;
    asm("{ .reg .u64 t; cvta.to.shared.u64 t, %1; cvt.u32.u64 %0, t; }"
        : "=r"(a) : "l"(p));
    return a;
}
__device__ __forceinline__ void cpa16(uint32_t s, const void* g) {
    asm volatile("cp.async.cg.shared.global [%0], [%1], 16;"
                 :: "r"(s), "l"(g) : "memory");
}
// b32-word permutation within each k16 group: slot = 2*(u&3) + (u>>2)
__device__ __forceinline__ int wperm(int u) { return 2 * (u & 3) + (u >> 2); }

__device__ __forceinline__ void mma16(float* d, uint32_t a0, uint32_t a1,
                                      uint32_t a2, uint32_t a3,
                                      uint32_t b0, uint32_t b1) {
    asm volatile(
        "mma.sync.aligned.m16n8k16.row.col.f32.bf16.bf16.f32 "
        "{%0,%1,%2,%3},{%4,%5,%6,%7},{%8,%9},{%0,%1,%2,%3};"
        : "+f"(d[0]), "+f"(d[1]), "+f"(d[2]), "+f"(d[3])
        : "r"(a0), "r"(a1), "r"(a2), "r"(a3), "r"(b0), "r"(b1));
}
// order-preserving float <-> uint for atomicMax
__device__ __forceinline__ uint32_t fkey(float f) {
    uint32_t u = __float_as_uint(f);
    return (u & 0x80000000u) ? ~u : (u | 0x80000000u);
}
__device__ __forceinline__ float funkey(uint32_t k) {
    return (k & 0x80000000u) ? __uint_as_float(k & 0x7fffffffu)
                             : __uint_as_float(~k);
}
// half-index (bf16 granularity) for channel c within a 256-ch permuted row
__device__ __forceinline__ int half_slot(int c) {
    int u = (c >> 1) & 7;
    return ((c >> 4) << 4) + wperm(u) * 2 + (c & 1);
}

// ---------------------------------------------------------------------------
// Prep: z [B,C,HW] -> g_Abf (bf16 permuted) + g_zf (plain fp32 rows)
// ---------------------------------------------------------------------------
__global__ void k_prep_z(const float* __restrict__ z) {
    __shared__ float t[32][33];
    const int c0 = blockIdx.x * 32, hw0 = blockIdx.y * 32, b = blockIdx.z;
    const int tx = threadIdx.x, ty = threadIdx.y;
    #pragma unroll
    for (int i = 0; i < 32; i += 8)
        t[ty + i][tx] = z[((size_t)b * CDIM + c0 + ty + i) * HW + hw0 + tx];
    __syncthreads();
    #pragma unroll
    for (int i = 0; i < 32; i += 8) {
        float v  = t[tx][ty + i];
        int   c  = c0 + tx;
        size_t n = (size_t)b * HW + hw0 + ty + i;
        g_zf[n * CDIM + c] = v;
        ((__nv_bfloat16*)g_Abf)[n * 256 + half_slot(c)] = __float2bfloat16_rn(v);
    }
}

// emb [K,C] -> g_Bbf (bf16 permuted)
__global__ void k_prep_e(const float* __restrict__ emb) {
    int i = blockIdx.x * 256 + threadIdx.x;
    int k = i >> 8, c = i & 255;
    ((__nv_bfloat16*)g_Bbf)[(size_t)k * 256 + half_slot(c)] =
        __float2bfloat16_rn(emb[i]);
}

// g_eh[k] = 0.5*||e_k||^2 (fp32)
__global__ void k_ehalf(const float* __restrict__ emb) {
    int k    = blockIdx.x * (blockDim.x >> 5) + (threadIdx.x >> 5);
    int lane = threadIdx.x & 31;
    const float* row = emb + (size_t)k * CDIM;
    float s = 0.0f;
    #pragma unroll
    for (int c = lane; c < CDIM; c += 32) { float v = row[c]; s = fmaf(v, v, s); }
    #pragma unroll
    for (int off = 16; off; off >>= 1) s += __shfl_xor_sync(0xffffffffu, s, off);
    if (lane == 0) g_eh[k] = 0.5f * s;
}

// ---------------------------------------------------------------------------
// Screen: bf16 m16n8k16 GEMM (K=256) + margin candidate collection.
// 512 threads, 4x4 warp grid, warp tile 32x32 (acc = 32 regs/thread).
// A panel (128 x 256 bf16 = 64KB) resident; B tiles (128 x 256 bf16 = 64KB)
// streamed through a 2-deep cp.async ring. One wait + one barrier per tile.
// Row layout: 4 x 128B chunks, word-permuted + XOR-swizzled (conflict-free
// LDS.64 fragment loads; scheme validated R11-R16).
// ---------------------------------------------------------------------------
__global__ __launch_bounds__(512, 1) void k_screen() {
    extern __shared__ float sm[];
    uint32_t* s_best = (uint32_t*)(sm + SM_BEST);

    const int tid  = threadIdx.x;
    const int lane = tid & 31, wid = tid >> 5;
    const int wm = wid & 3, wn = wid >> 2;     // 4 row groups x 4 col groups
    const int g = lane >> 2, tig = lane & 3;
    const int tig2 = tig >> 1, tig1 = tig & 1;
    const int m0 = blockIdx.x * 128;
    const uint32_t smb = smem_u32(sm);

    if (tid < 128) {
        s_best[tid] = fkey(-3.0e38f);
        g_cnt[m0 + tid] = 0;      // rows are CTA-private
    }

    // ---- fill resident A panel: 128 rows x 32 16B-units ----
    #pragma unroll
    for (int it = 0; it < 8; ++it) {
        int cidx = it * 512 + tid;
        int row = cidx >> 5, u = cidx & 31;
        int chunk = u >> 3, lc = u & 7;
        uint32_t d = smb + (uint32_t)row * 512u + (uint32_t)chunk * 128u +
                     (uint32_t)((lc ^ ((row & 3) << 1)) << 4);
        cpa16(d, g_Abf + (size_t)(m0 + row) * 128 + u * 4);
    }
    // ---- B tile loader ----
    auto issueB = [&](int tile, int stg) {
        uint32_t base = smb + (uint32_t)(SM_B0 * 4) + (uint32_t)stg * 65536u;
        const uint32_t* Bg = g_Bbf + (size_t)(tile * 128) * 128;
        #pragma unroll
        for (int it = 0; it < 8; ++it) {
            int cidx = it * 512 + tid;
            int row = cidx >> 5, u = cidx & 31;
            int chunk = u >> 3, lc = u & 7;
            uint32_t d = base + (uint32_t)row * 512u + (uint32_t)chunk * 128u +
                         (uint32_t)((lc ^ ((row & 3) << 1)) << 4);
            cpa16(d, Bg + (size_t)row * 128 + u * 4);
        }
    };
    issueB(0, 0);
    asm volatile("cp.async.commit_group;" ::: "memory");
    asm volatile("cp.async.wait_group 0;" ::: "memory");
    __syncthreads();

    // fragment word-pair load; l = k16 group 0..15, row stride 128 floats
    auto ldp = [&](const float* base, int row, int l) -> float2 {
        int chunk = l >> 2, lw = l & 3;
        int pc = (2 * lw + tig2) ^ ((row & 3) << 1);
        return *(const float2*)(base + row * 128 + chunk * 32 + pc * 4 + tig1 * 2);
    };

    for (int t = 0; t < NTILE; ++t) {
        if (t + 1 < NTILE) {
            issueB(t + 1, (t + 1) & 1);
            asm volatile("cp.async.commit_group;" ::: "memory");
        }

        const float* stB = sm + ((t & 1) ? SM_B1 : SM_B0);
        float acc[2][4][4];
        #pragma unroll
        for (int mi = 0; mi < 2; mi++)
            #pragma unroll
            for (int ni = 0; ni < 4; ni++)
                #pragma unroll
                for (int r = 0; r < 4; r++) acc[mi][ni][r] = 0.0f;

        #pragma unroll
        for (int l = 0; l < 16; ++l) {
            float2 fa[2][2];
            #pragma unroll
            for (int mi = 0; mi < 2; ++mi) {
                int r0 = wm * 32 + mi * 16 + g;
                fa[mi][0] = ldp(sm, r0, l);        // (a0, a2)
                fa[mi][1] = ldp(sm, r0 + 8, l);    // (a1, a3)
            }
            float2 fb[4];
            #pragma unroll
            for (int ni = 0; ni < 4; ++ni)
                fb[ni] = ldp(stB, wn * 32 + ni * 8 + g, l);   // (b0, b1)
            #pragma unroll
            for (int mi = 0; mi < 2; ++mi)
                #pragma unroll
                for (int ni = 0; ni < 4; ++ni)
                    mma16(acc[mi][ni],
                          __float_as_uint(fa[mi][0].x), __float_as_uint(fa[mi][1].x),
                          __float_as_uint(fa[mi][0].y), __float_as_uint(fa[mi][1].y),
                          __float_as_uint(fb[ni].x),    __float_as_uint(fb[ni].y));
        }

        // collection epilogue: approx score = acc - 0.5||e||^2
        {
            const int k0 = t * 128;
            float lb[2][2];
            #pragma unroll
            for (int mi = 0; mi < 2; ++mi)
                #pragma unroll
                for (int h = 0; h < 2; ++h)
                    lb[mi][h] = funkey(s_best[wm * 32 + mi * 16 + g + 8 * h]);

            #pragma unroll
            for (int ni = 0; ni < 4; ++ni) {
                #pragma unroll
                for (int r = 0; r < 4; ++r) {
                    const int lc  = wn * 32 + ni * 8 + 2 * tig + (r & 1);
                    const float e = __ldg(&g_eh[k0 + lc]);
                    const int h   = r >> 1;
                    #pragma unroll
                    for (int mi = 0; mi < 2; ++mi) {
                        float v = acc[mi][ni][r] - e;
                        if (v > lb[mi][h] - MARGIN) {
                            int rl  = wm * 32 + mi * 16 + g + 8 * h;
                            int row = m0 + rl;
                            int pos = atomicAdd(&g_cnt[row], 1);
                            if (pos < CAP) g_cand[(size_t)row * CAP + pos] = k0 + lc;
                            if (v > lb[mi][h]) {
                                lb[mi][h] = v;
                                atomicMax(&s_best[rl], fkey(v));
                            }
                        }
                    }
                }
            }
        }

        if (t + 1 < NTILE)
            asm volatile("cp.async.wait_group 0;" ::: "memory");
        __syncthreads();
    }
}

// ---------------------------------------------------------------------------
// Rescore: exact fp32 score for each candidate; one warp per query row.
// Max with lowest-index tie-break is order-independent -> deterministic.
// ---------------------------------------------------------------------------
__global__ void k_rescore(const float* __restrict__ emb) {
    const int wid  = threadIdx.x >> 5;
    const int lane = threadIdx.x & 31;
    const int row  = blockIdx.x * 8 + wid;

    int cnt = g_cnt[row];
    if (cnt > CAP) cnt = CAP;

    const float* zr = g_zf + (size_t)row * CDIM;
    float zc[8];
    #pragma unroll
    for (int i = 0; i < 8; ++i) zc[i] = zr[lane + 32 * i];

    float best = -3.0e38f;
    int   bidx = 0x7fffffff;
    for (int j = 0; j < cnt; ++j) {
        int idx = g_cand[(size_t)row * CAP + j];
        const float* er = emb + (size_t)idx * CDIM;
        float s = 0.0f;
        #pragma unroll
        for (int i = 0; i < 8; ++i) s = fmaf(zc[i], er[lane + 32 * i], s);
        #pragma unroll
        for (int off = 16; off; off >>= 1) s += __shfl_xor_sync(0xffffffffu, s, off);
        s -= g_eh[idx];
        if (s > best || (s == best && idx < bidx)) { best = s; bidx = idx; }
    }
    if (lane == 0) g_idx[row] = bidx;
}

// ---------------------------------------------------------------------------
// Gather: out[b][c][hw] = emb[idx[b*HW+hw]][c].
// ---------------------------------------------------------------------------
__global__ void k_gather(const float* __restrict__ emb, float* __restrict__ out) {
    __shared__ float tile[32 * 257];
    __shared__ int   sidx[32];
    const int nb  = blockIdx.x * 32;
    const int tid = threadIdx.x;
    if (tid < 32) sidx[tid] = g_idx[nb + tid];
    __syncthreads();

    const int w = tid >> 5, lane = tid & 31;
    #pragma unroll
    for (int r = w * 4; r < w * 4 + 4; ++r) {
        const float* src = emb + (size_t)sidx[r] * CDIM;
        #pragma unroll
        for (int c = lane; c < CDIM; c += 32)
            tile[r * 257 + c] = src[c];
    }
    __syncthreads();

    const int b   = nb >> 10;
    const int hw0 = nb & (HW - 1);
    const int cg  = tid >> 5;
    #pragma unroll
    for (int c = cg; c < CDIM; c += 8)
        out[b * (CDIM * HW) + c * HW + hw0 + lane] = tile[lane * 257 + c];
}

// ---------------------------------------------------------------------------
extern "C" void kernel_launch(void* const* d_in, const int* in_sizes, int n_in,
                              void* d_out, int out_size) {
    const float* z   = (const float*)d_in[0];   // [16,256,32,32] fp32
    const float* emb = (const float*)d_in[1];   // [8192,256] fp32
    float* out = (float*)d_out;

    cudaFuncSetAttribute(k_screen, cudaFuncAttributeMaxDynamicSharedMemorySize,
                         SMEM_TOTAL);

    k_prep_z <<<dim3(CDIM / 32, HW / 32, BD), dim3(32, 8)>>>(z);
    k_prep_e <<<(KCOD * CDIM) / 256, 256>>>(emb);
    k_ehalf  <<<KCOD / 8, 256>>>(emb);
    k_screen <<<NTOT / 128, 512, SMEM_TOTAL>>>();
    k_rescore<<<NTOT / 8, 256>>>(emb);
    k_gather <<<NTOT / 32, 256>>>(emb, out);
}